// round 1
// baseline (speedup 1.0000x reference)
#include <cuda_runtime.h>
#include <math.h>

// ---------------- problem constants ----------------
#define NES   4096          // E*S
#define VOBS  128
#define KOBS  32            // 2*OBJ nonzero indices per step
#define H     256
#define LSEQ  32
#define VCOMM 32
#define NL    131072        // NES*LSEQ

// ---------------- device scratch (no allocation allowed) ----------------
__device__ __align__(16) float g_M[VOBS * KOBS * H];            // 4 MB  obs table
__device__ __align__(16) float g_U[32768];                      // conv token table (compact)
__device__ int   g_idx[NES * KOBS];
__device__ int   g_tok[NES * LSEQ];
__device__ __align__(16) float g_conv[NL * H];                  // 134 MB raw conv output [n][l][c]
__device__ __align__(16) float g_bnPart[512 * 512];             // per-block BN partials
__device__ float g_bnS[H], g_bnT[H];                            // folded BN affine
__device__ __align__(16) float g_xproj[3 * LSEQ * NES * H];     // 402 MB [g][l][n][h]
__device__ __align__(16) float g_G[NES * 768];                  // per-step gate pre-activations
__device__ __align__(16) float g_h[2][NES * H];                 // GRU state ping-pong

// ---------------- K0: init (zero h0) ----------------
__global__ void k_init() {
    int t = blockIdx.x * blockDim.x + threadIdx.x;
    for (int i = t; i < NES * H; i += 256 * 256) g_h[0][i] = 0.f;
}

// ---------------- K1: extract obs indices (ballot scan) + comm argmax ----------------
__global__ void k_extract(const float* __restrict__ obs, const float* __restrict__ comm) {
    int m = blockIdx.x;                 // (e,s) flat
    int lane = threadIdx.x & 31;
    if (threadIdx.x < 32) {
        // ascending indices of the K ones (== argsort(-obs)[:K] stable)
        const float* o = obs + m * VOBS;
        int base = 0;
        #pragma unroll
        for (int c = 0; c < 4; c++) {
            float v = o[c * 32 + lane];
            unsigned mask = __ballot_sync(0xffffffffu, v > 0.5f);
            if (v > 0.5f) {
                int pos = base + __popc(mask & ((1u << lane) - 1u));
                g_idx[m * KOBS + pos] = c * 32 + lane;
            }
            base += __popc(mask);
        }
    } else {
        // argmax over V_COMM (first occurrence)
        int l = lane;
        const float* cm = comm + (m * LSEQ + l) * VCOMM;
        float best = cm[0]; int bi = 0;
        #pragma unroll
        for (int v = 1; v < VCOMM; v++) { float x = cm[v]; if (x > best) { best = x; bi = v; } }
        g_tok[m * LSEQ + l] = bi;
    }
}

// ---------------- K2: obs table M[i][k][j] = sum_h prelu(emb[i,h]) * W[k*H+h, j] ----------------
__global__ void k_obsM(const float* __restrict__ emb, const float* __restrict__ W,
                       const float* __restrict__ a_emb_p) {
    __shared__ float Ps[16][256];
    int k = blockIdx.x, i0 = blockIdx.y * 16;
    float a = a_emb_p[0];
    int tid = threadIdx.x;
    for (int r = tid; r < 16 * 256; r += 256) {
        int i = r >> 8, h = r & 255;
        float v = emb[(i0 + i) * H + h];
        Ps[i][h] = v >= 0.f ? v : a * v;
    }
    __syncthreads();
    float acc[16];
    #pragma unroll
    for (int i = 0; i < 16; i++) acc[i] = 0.f;
    int j = tid;
    const float* Wk = W + (k * H) * H + j;          // W[(k*H+h)*H + j]
    for (int h = 0; h < H; h++) {
        float w = Wk[h * H];
        #pragma unroll
        for (int i = 0; i < 16; i++) acc[i] = fmaf(Ps[i][h], w, acc[i]);
    }
    #pragma unroll
    for (int i = 0; i < 16; i++)
        g_M[((i0 + i) * KOBS + k) * H + j] = acc[i];
}

// ---------------- K3: conv token table U (compact, [group][d][t][64ch]) ----------------
__global__ void k_commU(const float* __restrict__ ce, const float* __restrict__ a_emb_p,
                        const float* __restrict__ w1, const float* __restrict__ w3,
                        const float* __restrict__ w5, const float* __restrict__ w7) {
    int c = blockIdx.x, d = blockIdx.y;
    int g = c >> 6, cg = c & 63;
    int ks = 2 * g + 1;
    if (d >= ks) return;
    int t = threadIdx.x;                            // 32 tokens
    const float* w = (g == 0) ? w1 : (g == 1) ? w3 : (g == 2) ? w5 : w7;
    float a = a_emb_p[0];
    float s = 0.f;
    for (int h = 0; h < H; h++) {
        float e = ce[t * H + h];
        e = e >= 0.f ? e : a * e;
        s = fmaf(w[(cg * H + h) * ks + d], e, s);
    }
    int segoff = (g == 0) ? 0 : (g == 1) ? 2048 : (g == 2) ? 8192 : 18432;
    g_U[segoff + (d * 32 + t) * 64 + cg] = s;
}

// ---------------- K4: conv via table lookups + BN partial stats (bias cancels in BN) ----------------
__global__ void k_conv() {
    extern __shared__ float sm[];
    float* sU   = sm;                 // 32768
    float* sRed = sm + 32768;         // 2048  [ty][512]
    __shared__ int sTok[256];
    int tx = threadIdx.x, ty = threadIdx.y;
    int tid = ty * 64 + tx;
    int n0 = blockIdx.x * 8;
    const float4* gU4 = (const float4*)g_U;
    float4* sU4 = (float4*)sU;
    for (int v = tid; v < 8192; v += 256) sU4[v] = gU4[v];
    if (tid < 256) sTok[tid] = g_tok[n0 * LSEQ + tid];
    __syncthreads();

    int g = tx >> 4, ks = 2 * g + 1, pad = g;
    int seg4 = (g == 0) ? 0 : (g == 1) ? 512 : (g == 2) ? 2048 : 4608;
    int cm = tx & 15;
    const float4* U4 = (const float4*)sU;
    float lsum[4] = {0, 0, 0, 0}, lsq[4] = {0, 0, 0, 0};

    for (int half = 0; half < 2; half++) {
        int nl = ty + 4 * half;
        int n = n0 + nl;
        const int* tk = sTok + nl * LSEQ;
        for (int l = 0; l < LSEQ; l++) {
            float4 acc = make_float4(0.f, 0.f, 0.f, 0.f);
            #pragma unroll
            for (int d = 0; d < 7; d++) {
                int lp = l + d - pad;
                if (d < ks && lp >= 0 && lp < LSEQ) {
                    float4 u = U4[seg4 + (d * 32 + tk[lp]) * 16 + cm];
                    acc.x += u.x; acc.y += u.y; acc.z += u.z; acc.w += u.w;
                }
            }
            ((float4*)g_conv)[(n * LSEQ + l) * 64 + tx] = acc;
            lsum[0] += acc.x; lsum[1] += acc.y; lsum[2] += acc.z; lsum[3] += acc.w;
            lsq[0] += acc.x * acc.x; lsq[1] += acc.y * acc.y;
            lsq[2] += acc.z * acc.z; lsq[3] += acc.w * acc.w;
        }
    }
    #pragma unroll
    for (int e = 0; e < 4; e++) {
        sRed[ty * 512 + 4 * tx + e]       = lsum[e];
        sRed[ty * 512 + 256 + 4 * tx + e] = lsq[e];
    }
    __syncthreads();
    if (tid < 256) {
        float s = sRed[tid] + sRed[512 + tid] + sRed[1024 + tid] + sRed[1536 + tid];
        float q = sRed[256 + tid] + sRed[768 + tid] + sRed[1280 + tid] + sRed[1792 + tid];
        g_bnPart[blockIdx.x * 512 + tid]       = s;
        g_bnPart[blockIdx.x * 512 + 256 + tid] = q;
    }
}

// ---------------- K5: finalize BN (deterministic double reduction) ----------------
__global__ void k_bnfin(const float* __restrict__ bn_g, const float* __restrict__ bn_b) {
    int c = threadIdx.x;
    double s = 0.0, q = 0.0;
    for (int b = 0; b < 512; b++) {
        s += (double)g_bnPart[b * 512 + c];
        q += (double)g_bnPart[b * 512 + 256 + c];
    }
    double mean = s / (double)NL;
    double var  = q / (double)NL - mean * mean;
    float sc = (float)((double)bn_g[c] / sqrt(var + 1e-5));
    g_bnS[c] = sc;
    g_bnT[c] = bn_b[c] - sc * (float)mean;
}

// ---------------- K6: xproj GEMM 131072x768x256, A = prelu(BN(conv)) fused on load ----------------
__global__ void k_xproj(const float* __restrict__ Wx, const float* __restrict__ bx,
                        const float* __restrict__ cnn_a_p) {
    __shared__ float As[16 * 132];
    __shared__ float Bs[16 * 128];
    int m0 = blockIdx.x * 128;
    int jj0 = blockIdx.y * 128;
    int g = jj0 >> 8, j0 = jj0 & 255;
    const float* B = Wx + g * 65536 + j0;
    float ca = cnn_a_p[0];
    int tid = threadIdx.x;
    int tx = tid & 15, ty = tid >> 4;
    float acc[8][8];
    #pragma unroll
    for (int i = 0; i < 8; i++)
        #pragma unroll
        for (int j = 0; j < 8; j++) acc[i][j] = 0.f;

    for (int k0 = 0; k0 < H; k0 += 16) {
        #pragma unroll
        for (int it = 0; it < 2; it++) {
            int v = tid + it * 256;
            int row = v >> 2, segc = v & 3;
            float4 a4 = *(const float4*)&g_conv[(m0 + row) * H + k0 + 4 * segc];
            float av[4] = {a4.x, a4.y, a4.z, a4.w};
            #pragma unroll
            for (int e = 0; e < 4; e++) {
                int c = k0 + 4 * segc + e;
                float x = fmaf(g_bnS[c], av[e], g_bnT[c]);
                As[(4 * segc + e) * 132 + row] = x >= 0.f ? x : ca * x;
            }
            int rowk = v >> 5, jc = v & 31;
            float4 b4 = *(const float4*)&B[(k0 + rowk) * H + 4 * jc];
            *(float4*)&Bs[rowk * 128 + 4 * jc] = b4;
        }
        __syncthreads();
        #pragma unroll
        for (int k = 0; k < 16; k++) {
            float a[8], b[8];
            *(float4*)&a[0] = *(const float4*)&As[k * 132 + ty * 8];
            *(float4*)&a[4] = *(const float4*)&As[k * 132 + ty * 8 + 4];
            *(float4*)&b[0] = *(const float4*)&Bs[k * 128 + tx * 8];
            *(float4*)&b[4] = *(const float4*)&Bs[k * 128 + tx * 8 + 4];
            #pragma unroll
            for (int i = 0; i < 8; i++)
                #pragma unroll
                for (int j = 0; j < 8; j++)
                    acc[i][j] = fmaf(a[i], b[j], acc[i][j]);
        }
        __syncthreads();
    }
    #pragma unroll
    for (int i = 0; i < 8; i++) {
        int m = m0 + ty * 8 + i;
        int n = m >> 5, l = m & 31;
        float* dst = g_xproj + ((size_t)(g * LSEQ + l) * NES + n) * H + j0 + tx * 8;
        #pragma unroll
        for (int j = 0; j < 8; j++)
            dst[j] = acc[i][j] + bx[g * H + j0 + tx * 8 + j];
    }
}

// ---------------- K7: recurrence GEMM G = h @ WhB + bh (per step) ----------------
__global__ void k_recgemm(int hin, const float* __restrict__ Wh, const float* __restrict__ bh) {
    __shared__ float As[16 * 68];
    __shared__ float Bs[16 * 64];
    int m0 = blockIdx.x * 64;
    int jj0 = blockIdx.y * 64;
    int g = jj0 >> 8, j0 = jj0 & 255;
    const float* B = Wh + g * 65536 + j0;
    const float* A = g_h[hin];
    int tid = threadIdx.x;
    int tx = tid & 15, ty = tid >> 4;
    float acc[4][4];
    #pragma unroll
    for (int i = 0; i < 4; i++)
        #pragma unroll
        for (int j = 0; j < 4; j++) acc[i][j] = 0.f;

    for (int k0 = 0; k0 < H; k0 += 16) {
        int row = tid >> 2, segc = tid & 3;
        float4 a4 = *(const float4*)&A[(m0 + row) * H + k0 + 4 * segc];
        As[(4 * segc + 0) * 68 + row] = a4.x;
        As[(4 * segc + 1) * 68 + row] = a4.y;
        As[(4 * segc + 2) * 68 + row] = a4.z;
        As[(4 * segc + 3) * 68 + row] = a4.w;
        int rowk = tid >> 4, jc = tid & 15;
        float4 b4 = *(const float4*)&B[(k0 + rowk) * H + 4 * jc];
        *(float4*)&Bs[rowk * 64 + 4 * jc] = b4;
        __syncthreads();
        #pragma unroll
        for (int k = 0; k < 16; k++) {
            float a[4], b[4];
            *(float4*)a = *(const float4*)&As[k * 68 + ty * 4];
            *(float4*)b = *(const float4*)&Bs[k * 64 + tx * 4];
            #pragma unroll
            for (int i = 0; i < 4; i++)
                #pragma unroll
                for (int j = 0; j < 4; j++)
                    acc[i][j] = fmaf(a[i], b[j], acc[i][j]);
        }
        __syncthreads();
    }
    #pragma unroll
    for (int i = 0; i < 4; i++) {
        int m = m0 + ty * 4 + i;
        #pragma unroll
        for (int j = 0; j < 4; j++) {
            int jj = jj0 + tx * 4 + j;
            g_G[m * 768 + jj] = acc[i][j] + bh[g * H + j0 + tx * 4 + j];
        }
    }
}

// ---------------- K8: GRU gates elementwise (per step) ----------------
__global__ void k_gate(int l, int hin) {
    int i = blockIdx.x * 256 + threadIdx.x;
    int n = i >> 8, j = i & 255;
    float h = g_h[hin][i];
    const float* G = g_G + n * 768 + j;
    float gr = G[0], gz = G[256], gn = G[512];
    const float* xp = g_xproj + ((size_t)l * NES + n) * H + j;
    float xr = xp[0];
    float xz = xp[(size_t)LSEQ * NES * H];
    float xn = xp[2 * (size_t)LSEQ * NES * H];
    float r = 1.f / (1.f + expf(-(xr + gr)));
    float z = 1.f / (1.f + expf(-(xz + gz)));
    float t = tanhf(xn + r * gn);
    g_h[hin ^ 1][i] = t + z * (h - t);
}

// ---------------- K9: final linear on c-path, writes out[..., 256:512] ----------------
__global__ void k_final(int hin, const float* __restrict__ Wl, const float* __restrict__ bl,
                        const float* __restrict__ a1p, const float* __restrict__ a2p,
                        float* __restrict__ out) {
    __shared__ float As[16 * 68];
    __shared__ float Bs[16 * 64];
    int m0 = blockIdx.x * 64;
    int j0 = blockIdx.y * 64;
    float a1 = a1p[0], a2 = a2p[0];
    const float* A = g_h[hin];
    int tid = threadIdx.x;
    int tx = tid & 15, ty = tid >> 4;
    float acc[4][4];
    #pragma unroll
    for (int i = 0; i < 4; i++)
        #pragma unroll
        for (int j = 0; j < 4; j++) acc[i][j] = 0.f;

    for (int k0 = 0; k0 < H; k0 += 16) {
        int row = tid >> 2, segc = tid & 3;
        float4 a4 = *(const float4*)&A[(m0 + row) * H + k0 + 4 * segc];
        float av[4] = {a4.x, a4.y, a4.z, a4.w};
        #pragma unroll
        for (int e = 0; e < 4; e++) {
            float x = av[e];
            As[(4 * segc + e) * 68 + row] = x >= 0.f ? x : a1 * x;
        }
        int rowk = tid >> 4, jc = tid & 15;
        float4 b4 = *(const float4*)&Wl[(k0 + rowk) * H + j0 + 4 * jc];
        *(float4*)&Bs[rowk * 64 + 4 * jc] = b4;
        __syncthreads();
        #pragma unroll
        for (int k = 0; k < 16; k++) {
            float a[4], b[4];
            *(float4*)a = *(const float4*)&As[k * 68 + ty * 4];
            *(float4*)b = *(const float4*)&Bs[k * 64 + tx * 4];
            #pragma unroll
            for (int i = 0; i < 4; i++)
                #pragma unroll
                for (int j = 0; j < 4; j++)
                    acc[i][j] = fmaf(a[i], b[j], acc[i][j]);
        }
        __syncthreads();
    }
    #pragma unroll
    for (int i = 0; i < 4; i++) {
        int m = m0 + ty * 4 + i;
        #pragma unroll
        for (int j = 0; j < 4; j++) {
            int jj = j0 + tx * 4 + j;
            float v = acc[i][j] + bl[jj];
            v = v >= 0.f ? v : a2 * v;
            out[m * 512 + 256 + jj] = v;
        }
    }
}

// ---------------- K10: obs output = prelu(sum_k M[idx_k,k,:] + b), writes out[..., 0:256] ----------------
__global__ void k_obsout(const float* __restrict__ obs_b, const float* __restrict__ obs_a_p,
                         float* __restrict__ out) {
    int m = blockIdx.x;
    int j = threadIdx.x;
    __shared__ int si[KOBS];
    if (j < KOBS) si[j] = g_idx[m * KOBS + j];
    __syncthreads();
    float acc = obs_b[j];
    #pragma unroll
    for (int k = 0; k < KOBS; k++)
        acc += g_M[(si[k] * KOBS + k) * H + j];
    float a = obs_a_p[0];
    out[m * 512 + j] = acc >= 0.f ? acc : a * acc;
}

// ---------------- host launch ----------------
extern "C" void kernel_launch(void* const* d_in, const int* in_sizes, int n_in,
                              void* d_out, int out_size) {
    const float* obs        = (const float*)d_in[0];
    const float* comm       = (const float*)d_in[1];
    const float* obs_emb    = (const float*)d_in[2];
    const float* obs_a_emb  = (const float*)d_in[3];
    const float* obs_W      = (const float*)d_in[4];
    const float* obs_b      = (const float*)d_in[5];
    const float* obs_a      = (const float*)d_in[6];
    const float* comm_emb   = (const float*)d_in[7];
    const float* comm_a_emb = (const float*)d_in[8];
    const float* cw1        = (const float*)d_in[9];
    const float* cw3        = (const float*)d_in[11];
    const float* cw5        = (const float*)d_in[13];
    const float* cw7        = (const float*)d_in[15];
    const float* bn_g       = (const float*)d_in[17];
    const float* bn_b       = (const float*)d_in[18];
    const float* cnn_a      = (const float*)d_in[19];
    const float* Wx         = (const float*)d_in[20];
    const float* bx         = (const float*)d_in[21];
    const float* Wh         = (const float*)d_in[22];
    const float* bh         = (const float*)d_in[23];
    const float* lin_a1     = (const float*)d_in[24];
    const float* lin_W      = (const float*)d_in[25];
    const float* lin_b      = (const float*)d_in[26];
    const float* lin_a2     = (const float*)d_in[27];
    float* out = (float*)d_out;

    cudaFuncSetAttribute(k_conv, cudaFuncAttributeMaxDynamicSharedMemorySize, 139264);

    k_init<<<256, 256>>>();
    k_extract<<<NES, 64>>>(obs, comm);
    k_obsM<<<dim3(32, 8), 256>>>(obs_emb, obs_W, obs_a_emb);
    k_commU<<<dim3(256, 7), 32>>>(comm_emb, comm_a_emb, cw1, cw3, cw5, cw7);
    k_conv<<<512, dim3(64, 4), 139264>>>();
    k_bnfin<<<1, 256>>>(bn_g, bn_b);
    k_xproj<<<dim3(1024, 6), 256>>>(Wx, bx, cnn_a);

    int hin = 0;
    for (int l = 0; l < LSEQ; l++) {
        k_recgemm<<<dim3(64, 12), 256>>>(hin, Wh, bh);
        k_gate<<<NES, 256>>>(l, hin);
        hin ^= 1;
    }
    // after 32 toggles, final h is in g_h[0]
    k_final<<<dim3(64, 4), 256>>>(hin, lin_W, lin_b, lin_a1, lin_a2, out);
    k_obsout<<<NES, 256>>>(obs_b, obs_a, out);
}

// round 2
// speedup vs baseline: 1.0227x; 1.0227x over previous
#include <cuda_runtime.h>
#include <math.h>

// ---------------- problem constants ----------------
#define NES   4096          // E*S
#define VOBS  128
#define KOBS  32            // 2*OBJ nonzero indices per step
#define H     256
#define LSEQ  32
#define VCOMM 32
#define NL    131072        // NES*LSEQ

typedef unsigned long long ull;

// fma.rn.f32x2: packed 2x fp32 FMA (sm_100+), acc held as opaque 64-bit pair
__device__ __forceinline__ void ffma2(ull &c, ull a, ull b) {
    asm("fma.rn.f32x2 %0, %1, %2, %0;" : "+l"(c) : "l"(a), "l"(b));
}
__device__ __forceinline__ float2 unpack2(ull c) {
    float2 r; asm("mov.b64 {%0, %1}, %2;" : "=f"(r.x), "=f"(r.y) : "l"(c)); return r;
}

// ---------------- device scratch (no allocation allowed) ----------------
__device__ __align__(16) float g_M[VOBS * KOBS * H];            // 4 MB  obs table
__device__ __align__(16) float g_U[32768];                      // conv token table
__device__ int   g_idx[NES * KOBS];
__device__ int   g_tok[NES * LSEQ];
__device__ __align__(16) float g_conv[NL * H];                  // conv output [n*32+l][c]
__device__ __align__(16) float g_bnPart[512 * 512];
__device__ float g_bnS[H], g_bnT[H];
__device__ __align__(16) float g_xproj[(size_t)LSEQ * NES * 3 * H]; // [l][n][g][j]
__device__ __align__(16) float g_h[NES * H];                    // final GRU state

// ---------------- K: extract obs indices (ballot scan) + comm argmax ----------------
__global__ void k_extract(const float* __restrict__ obs, const float* __restrict__ comm) {
    int m = blockIdx.x;
    int lane = threadIdx.x & 31;
    if (threadIdx.x < 32) {
        const float* o = obs + m * VOBS;
        int base = 0;
        #pragma unroll
        for (int c = 0; c < 4; c++) {
            float v = o[c * 32 + lane];
            unsigned mask = __ballot_sync(0xffffffffu, v > 0.5f);
            if (v > 0.5f) {
                int pos = base + __popc(mask & ((1u << lane) - 1u));
                g_idx[m * KOBS + pos] = c * 32 + lane;
            }
            base += __popc(mask);
        }
    } else {
        int l = lane;
        const float* cm = comm + (m * LSEQ + l) * VCOMM;
        float best = cm[0]; int bi = 0;
        #pragma unroll
        for (int v = 1; v < VCOMM; v++) { float x = cm[v]; if (x > best) { best = x; bi = v; } }
        g_tok[m * LSEQ + l] = bi;
    }
}

// ---------------- K: obs table M[i][k][j] ----------------
__global__ void k_obsM(const float* __restrict__ emb, const float* __restrict__ W,
                       const float* __restrict__ a_emb_p) {
    __shared__ float Ps[16][256];
    int k = blockIdx.x, i0 = blockIdx.y * 16;
    float a = a_emb_p[0];
    int tid = threadIdx.x;
    for (int r = tid; r < 16 * 256; r += 256) {
        int i = r >> 8, h = r & 255;
        float v = emb[(i0 + i) * H + h];
        Ps[i][h] = v >= 0.f ? v : a * v;
    }
    __syncthreads();
    float acc[16];
    #pragma unroll
    for (int i = 0; i < 16; i++) acc[i] = 0.f;
    int j = tid;
    const float* Wk = W + (k * H) * H + j;
    for (int h = 0; h < H; h++) {
        float w = Wk[h * H];
        #pragma unroll
        for (int i = 0; i < 16; i++) acc[i] = fmaf(Ps[i][h], w, acc[i]);
    }
    #pragma unroll
    for (int i = 0; i < 16; i++)
        g_M[((i0 + i) * KOBS + k) * H + j] = acc[i];
}

// ---------------- K: conv token table U (smem-tiled) ----------------
__global__ void k_commU(const float* __restrict__ ce, const float* __restrict__ a_emb_p,
                        const float* __restrict__ w1, const float* __restrict__ w3,
                        const float* __restrict__ w5, const float* __restrict__ w7) {
    extern __shared__ float smc[];
    float* sE = smc;            // 8192   [t*256+h] prelu'd embeddings
    float* sW = smc + 8192;     // 64*257 [cg][h] weights for this (g,d)
    int g = blockIdx.x, d = blockIdx.y;
    int ks = 2 * g + 1;
    if (d >= ks) return;
    const float* w = (g == 0) ? w1 : (g == 1) ? w3 : (g == 2) ? w5 : w7;
    int tid = threadIdx.x;
    float a = a_emb_p[0];
    for (int v = tid; v < 8192; v += 256) {
        float e = ce[v];
        sE[v] = e >= 0.f ? e : a * e;
    }
    for (int v = tid; v < 16384; v += 256) {
        int cg = v >> 8, h = v & 255;
        sW[cg * 257 + h] = w[(cg * 256 + h) * ks + d];
    }
    __syncthreads();
    int cg = tid & 63, t0 = (tid >> 6) * 8;
    float acc[8];
    #pragma unroll
    for (int t = 0; t < 8; t++) acc[t] = 0.f;
    for (int h = 0; h < 256; h++) {
        float wv = sW[cg * 257 + h];
        #pragma unroll
        for (int t = 0; t < 8; t++) acc[t] = fmaf(sE[(t0 + t) * 256 + h], wv, acc[t]);
    }
    int segoff = (g == 0) ? 0 : (g == 1) ? 2048 : (g == 2) ? 8192 : 18432;
    #pragma unroll
    for (int t = 0; t < 8; t++)
        g_U[segoff + (d * 32 + t0 + t) * 64 + cg] = acc[t];
}

// ---------------- K: conv via table lookups + BN partial stats ----------------
__global__ void k_conv() {
    extern __shared__ float sm[];
    float* sU   = sm;
    float* sRed = sm + 32768;
    __shared__ int sTok[256];
    int tx = threadIdx.x, ty = threadIdx.y;
    int tid = ty * 64 + tx;
    int n0 = blockIdx.x * 8;
    const float4* gU4 = (const float4*)g_U;
    float4* sU4 = (float4*)sU;
    for (int v = tid; v < 8192; v += 256) sU4[v] = gU4[v];
    if (tid < 256) sTok[tid] = g_tok[n0 * LSEQ + tid];
    __syncthreads();

    int g = tx >> 4, ks = 2 * g + 1, pad = g;
    int seg4 = (g == 0) ? 0 : (g == 1) ? 512 : (g == 2) ? 2048 : 4608;
    int cm = tx & 15;
    const float4* U4 = (const float4*)sU;
    float lsum[4] = {0, 0, 0, 0}, lsq[4] = {0, 0, 0, 0};

    for (int half = 0; half < 2; half++) {
        int nl = ty + 4 * half;
        int n = n0 + nl;
        const int* tk = sTok + nl * LSEQ;
        for (int l = 0; l < LSEQ; l++) {
            float4 acc = make_float4(0.f, 0.f, 0.f, 0.f);
            #pragma unroll
            for (int d = 0; d < 7; d++) {
                int lp = l + d - pad;
                if (d < ks && lp >= 0 && lp < LSEQ) {
                    float4 u = U4[seg4 + (d * 32 + tk[lp]) * 16 + cm];
                    acc.x += u.x; acc.y += u.y; acc.z += u.z; acc.w += u.w;
                }
            }
            ((float4*)g_conv)[(n * LSEQ + l) * 64 + tx] = acc;
            lsum[0] += acc.x; lsum[1] += acc.y; lsum[2] += acc.z; lsum[3] += acc.w;
            lsq[0] += acc.x * acc.x; lsq[1] += acc.y * acc.y;
            lsq[2] += acc.z * acc.z; lsq[3] += acc.w * acc.w;
        }
    }
    #pragma unroll
    for (int e = 0; e < 4; e++) {
        sRed[ty * 512 + 4 * tx + e]       = lsum[e];
        sRed[ty * 512 + 256 + 4 * tx + e] = lsq[e];
    }
    __syncthreads();
    if (tid < 256) {
        float s = sRed[tid] + sRed[512 + tid] + sRed[1024 + tid] + sRed[1536 + tid];
        float q = sRed[256 + tid] + sRed[768 + tid] + sRed[1280 + tid] + sRed[1792 + tid];
        g_bnPart[blockIdx.x * 512 + tid]       = s;
        g_bnPart[blockIdx.x * 512 + 256 + tid] = q;
    }
}

// ---------------- K: finalize BN ----------------
__global__ void k_bnfin(const float* __restrict__ bn_g, const float* __restrict__ bn_b) {
    int c = threadIdx.x;
    double s = 0.0, q = 0.0;
    for (int b = 0; b < 512; b++) {
        s += (double)g_bnPart[b * 512 + c];
        q += (double)g_bnPart[b * 512 + 256 + c];
    }
    double mean = s / (double)NL;
    double var  = q / (double)NL - mean * mean;
    float sc = (float)((double)bn_g[c] / sqrt(var + 1e-5));
    g_bnS[c] = sc;
    g_bnT[c] = bn_b[c] - sc * (float)mean;
}

// ---------------- K: xproj GEMM 131072x768x256 with FFMA2 ----------------
// A = prelu(BN(conv)) fused on load, stored DUPLICATED in smem so the
// broadcast operand of fma.rn.f32x2 needs no per-op register packing.
__global__ void __launch_bounds__(256) k_xproj(const float* __restrict__ Wx,
                                               const float* __restrict__ bx,
                                               const float* __restrict__ cnn_a_p) {
    __shared__ float AsD[16 * 260];     // [k][2*row] duplicated pairs (rows 0..127)
    __shared__ float Bs[16 * 128];      // [k][col]
    int m0 = blockIdx.x * 128;
    int jj0 = blockIdx.y * 128;
    int g = jj0 >> 8, j0 = jj0 & 255;
    const float* B = Wx + g * 65536 + j0;
    float ca = cnn_a_p[0];
    int tid = threadIdx.x;
    int tx = tid & 15, ty = tid >> 4;
    ull acc2[8][4];
    #pragma unroll
    for (int i = 0; i < 8; i++)
        #pragma unroll
        for (int p = 0; p < 4; p++) acc2[i][p] = 0ull;

    for (int k0 = 0; k0 < H; k0 += 16) {
        #pragma unroll
        for (int it = 0; it < 2; it++) {
            int v = tid + it * 256;
            int row = v >> 2, segc = v & 3;
            float4 a4 = *(const float4*)&g_conv[(m0 + row) * H + k0 + 4 * segc];
            float av[4] = {a4.x, a4.y, a4.z, a4.w};
            #pragma unroll
            for (int e = 0; e < 4; e++) {
                int c = k0 + 4 * segc + e;
                float x = fmaf(g_bnS[c], av[e], g_bnT[c]);
                x = x >= 0.f ? x : ca * x;
                *(float2*)&AsD[(4 * segc + e) * 260 + 2 * row] = make_float2(x, x);
            }
            int rowk = v >> 5, jc = v & 31;
            float4 b4 = *(const float4*)&B[(k0 + rowk) * H + 4 * jc];
            *(float4*)&Bs[rowk * 128 + 4 * jc] = b4;
        }
        __syncthreads();
        #pragma unroll
        for (int k = 0; k < 16; k++) {
            ull b2[4];
            {
                const ull* bp = (const ull*)&Bs[k * 128 + tx * 8];
                b2[0] = bp[0]; b2[1] = bp[1]; b2[2] = bp[2]; b2[3] = bp[3];
            }
            #pragma unroll
            for (int i = 0; i < 8; i++) {
                ull ad = *(const ull*)&AsD[k * 260 + 2 * (ty * 8 + i)];
                #pragma unroll
                for (int p = 0; p < 4; p++) ffma2(acc2[i][p], ad, b2[p]);
            }
        }
        __syncthreads();
    }
    #pragma unroll
    for (int i = 0; i < 8; i++) {
        int m = m0 + ty * 8 + i;
        // conv row m = n*32 + l ; xproj layout [l][n][g][j]
        size_t base = (((size_t)(m & 31) * NES + (m >> 5)) * 3 + g) * 256 + j0 + tx * 8;
        #pragma unroll
        for (int p = 0; p < 4; p++) {
            float2 v = unpack2(acc2[i][p]);
            int col = j0 + tx * 8 + 2 * p;
            g_xproj[base + 2 * p]     = v.x + bx[g * H + col];
            g_xproj[base + 2 * p + 1] = v.y + bx[g * H + col + 1];
        }
    }
}

// ---------------- K: fused 32-step GRU recurrence ----------------
// 128 CTAs x 32 rows. h kept duplicated in smem across all steps; Wh streamed
// through smem with register prefetch; gates inline. FFMA2 inner product.
__global__ void __launch_bounds__(256, 1) k_rnn(const float* __restrict__ Wh,
                                                const float* __restrict__ bh) {
    extern __shared__ float smr[];
    float* hD = smr;                    // 32*514  [r][2k] duplicated h pairs
    float* Bs = smr + 32 * 514;         // 16*772  [k][col]
    float* Gs = Bs + 16 * 772;          // 32*774  [r][col]
    int tid = threadIdx.x;
    int w = tid >> 5, lane = tid & 31;
    int lr = lane >> 3, lc = lane & 7;  // rows lr+4i, col pairs w*96+lc*2+16j
    int m0 = blockIdx.x * 32;
    int cbase = w * 96 + lc * 2;

    for (int v = tid; v < 32 * 514; v += 256) hD[v] = 0.f;
    float bhr = bh[tid], bhz = bh[256 + tid], bhn = bh[512 + tid];

    // prefetch tile 0 of Wh into registers
    float4 pre[12];
    #pragma unroll
    for (int idx = 0; idx < 12; idx++) {
        int v = tid + idx * 256;
        int krow = v / 192, c4 = v % 192;
        int col = c4 * 4, g = col >> 8;
        pre[idx] = *(const float4*)&Wh[g * 65536 + krow * 256 + (col & 255)];
    }
    __syncthreads();

    for (int l = 0; l < LSEQ; l++) {
        ull acc[8][6];
        #pragma unroll
        for (int i = 0; i < 8; i++)
            #pragma unroll
            for (int j = 0; j < 6; j++) acc[i][j] = 0ull;

        for (int kt = 0; kt < 16; kt++) {
            // commit prefetched tile to smem
            #pragma unroll
            for (int idx = 0; idx < 12; idx++) {
                int v = tid + idx * 256;
                int krow = v / 192, c4 = v % 192;
                *(float4*)&Bs[krow * 772 + c4 * 4] = pre[idx];
            }
            __syncthreads();
            // prefetch next tile (overlaps compute)
            int ktn = (kt + 1) & 15;
            #pragma unroll
            for (int idx = 0; idx < 12; idx++) {
                int v = tid + idx * 256;
                int krow = v / 192, c4 = v % 192;
                int col = c4 * 4, g = col >> 8;
                pre[idx] = *(const float4*)&Wh[g * 65536 + (ktn * 16 + krow) * 256 + (col & 255)];
            }
            // compute
            #pragma unroll
            for (int kk = 0; kk < 16; kk++) {
                int k = kt * 16 + kk;
                ull a2[8];
                #pragma unroll
                for (int i = 0; i < 8; i++)
                    a2[i] = *(const ull*)&hD[(lr + 4 * i) * 514 + 2 * k];
                #pragma unroll
                for (int j = 0; j < 6; j++) {
                    ull b2 = *(const ull*)&Bs[kk * 772 + cbase + 16 * j];
                    #pragma unroll
                    for (int i = 0; i < 8; i++) ffma2(acc[i][j], a2[i], b2);
                }
            }
            __syncthreads();
        }
        // write gate pre-activations
        #pragma unroll
        for (int i = 0; i < 8; i++) {
            int r = lr + 4 * i;
            #pragma unroll
            for (int j = 0; j < 6; j++)
                *(ull*)&Gs[r * 774 + cbase + 16 * j] = acc[i][j];
        }
        __syncthreads();
        // gates: thread = column tid, loop over 32 rows
        const float* xp = g_xproj + ((size_t)l * NES + m0) * 768 + tid;
        #pragma unroll 4
        for (int t = 0; t < 32; t++) {
            float xr = xp[t * 768], xz = xp[t * 768 + 256], xn = xp[t * 768 + 512];
            float gr = Gs[t * 774 + tid] + bhr;
            float gz = Gs[t * 774 + 256 + tid] + bhz;
            float gn = Gs[t * 774 + 512 + tid] + bhn;
            float h = hD[t * 514 + 2 * tid];
            float rr = __fdividef(1.f, 1.f + __expf(-(xr + gr)));
            float zz = __fdividef(1.f, 1.f + __expf(-(xz + gz)));
            float arg = xn + rr * gn;
            float e2 = __expf(2.f * arg);
            float th = 1.f - __fdividef(2.f, e2 + 1.f);
            float hn = th + zz * (h - th);
            *(float2*)&hD[t * 514 + 2 * tid] = make_float2(hn, hn);
        }
        __syncthreads();
    }
    for (int t = 0; t < 32; t++)
        g_h[(m0 + t) * 256 + tid] = hD[t * 514 + 2 * tid];
}

// ---------------- K: final linear on c-path ----------------
__global__ void k_final(const float* __restrict__ Wl, const float* __restrict__ bl,
                        const float* __restrict__ a1p, const float* __restrict__ a2p,
                        float* __restrict__ out) {
    __shared__ float As[16 * 68];
    __shared__ float Bs[16 * 64];
    int m0 = blockIdx.x * 64;
    int j0 = blockIdx.y * 64;
    float a1 = a1p[0], a2 = a2p[0];
    const float* A = g_h;
    int tid = threadIdx.x;
    int tx = tid & 15, ty = tid >> 4;
    float acc[4][4];
    #pragma unroll
    for (int i = 0; i < 4; i++)
        #pragma unroll
        for (int j = 0; j < 4; j++) acc[i][j] = 0.f;

    for (int k0 = 0; k0 < H; k0 += 16) {
        int row = tid >> 2, segc = tid & 3;
        float4 a4 = *(const float4*)&A[(m0 + row) * H + k0 + 4 * segc];
        float av[4] = {a4.x, a4.y, a4.z, a4.w};
        #pragma unroll
        for (int e = 0; e < 4; e++) {
            float x = av[e];
            As[(4 * segc + e) * 68 + row] = x >= 0.f ? x : a1 * x;
        }
        int rowk = tid >> 4, jc = tid & 15;
        float4 b4 = *(const float4*)&Wl[(k0 + rowk) * H + j0 + 4 * jc];
        *(float4*)&Bs[rowk * 64 + 4 * jc] = b4;
        __syncthreads();
        #pragma unroll
        for (int k = 0; k < 16; k++) {
            float a[4], b[4];
            *(float4*)a = *(const float4*)&As[k * 68 + ty * 4];
            *(float4*)b = *(const float4*)&Bs[k * 64 + tx * 4];
            #pragma unroll
            for (int i = 0; i < 4; i++)
                #pragma unroll
                for (int j = 0; j < 4; j++)
                    acc[i][j] = fmaf(a[i], b[j], acc[i][j]);
        }
        __syncthreads();
    }
    #pragma unroll
    for (int i = 0; i < 4; i++) {
        int m = m0 + ty * 4 + i;
        #pragma unroll
        for (int j = 0; j < 4; j++) {
            int jj = j0 + tx * 4 + j;
            float v = acc[i][j] + bl[jj];
            v = v >= 0.f ? v : a2 * v;
            out[m * 512 + 256 + jj] = v;
        }
    }
}

// ---------------- K: obs output ----------------
__global__ void k_obsout(const float* __restrict__ obs_b, const float* __restrict__ obs_a_p,
                         float* __restrict__ out) {
    int m = blockIdx.x;
    int j = threadIdx.x;
    __shared__ int si[KOBS];
    if (j < KOBS) si[j] = g_idx[m * KOBS + j];
    __syncthreads();
    float acc = obs_b[j];
    #pragma unroll
    for (int k = 0; k < KOBS; k++)
        acc += g_M[(si[k] * KOBS + k) * H + j];
    float a = obs_a_p[0];
    out[m * 512 + j] = acc >= 0.f ? acc : a * acc;
}

// ---------------- host launch ----------------
extern "C" void kernel_launch(void* const* d_in, const int* in_sizes, int n_in,
                              void* d_out, int out_size) {
    const float* obs        = (const float*)d_in[0];
    const float* comm       = (const float*)d_in[1];
    const float* obs_emb    = (const float*)d_in[2];
    const float* obs_a_emb  = (const float*)d_in[3];
    const float* obs_W      = (const float*)d_in[4];
    const float* obs_b      = (const float*)d_in[5];
    const float* obs_a      = (const float*)d_in[6];
    const float* comm_emb   = (const float*)d_in[7];
    const float* comm_a_emb = (const float*)d_in[8];
    const float* cw1        = (const float*)d_in[9];
    const float* cw3        = (const float*)d_in[11];
    const float* cw5        = (const float*)d_in[13];
    const float* cw7        = (const float*)d_in[15];
    const float* bn_g       = (const float*)d_in[17];
    const float* bn_b       = (const float*)d_in[18];
    const float* cnn_a      = (const float*)d_in[19];
    const float* Wx         = (const float*)d_in[20];
    const float* bx         = (const float*)d_in[21];
    const float* Wh         = (const float*)d_in[22];
    const float* bh         = (const float*)d_in[23];
    const float* lin_a1     = (const float*)d_in[24];
    const float* lin_W      = (const float*)d_in[25];
    const float* lin_b      = (const float*)d_in[26];
    const float* lin_a2     = (const float*)d_in[27];
    float* out = (float*)d_out;

    cudaFuncSetAttribute(k_conv,  cudaFuncAttributeMaxDynamicSharedMemorySize, 139264);
    cudaFuncSetAttribute(k_commU, cudaFuncAttributeMaxDynamicSharedMemorySize, 98560);
    cudaFuncSetAttribute(k_rnn,   cudaFuncAttributeMaxDynamicSharedMemorySize, 214272);

    k_extract<<<NES, 64>>>(obs, comm);                       // launch 0
    k_obsM<<<dim3(32, 8), 256>>>(obs_emb, obs_W, obs_a_emb); // launch 1
    k_commU<<<dim3(4, 7), 256, 98560>>>(comm_emb, comm_a_emb, cw1, cw3, cw5, cw7); // 2
    k_conv<<<512, dim3(64, 4), 139264>>>();                  // launch 3
    k_bnfin<<<1, 256>>>(bn_g, bn_b);                         // launch 4
    k_xproj<<<dim3(1024, 6), 256>>>(Wx, bx, cnn_a);          // launch 5 (ncu target)
    k_rnn<<<128, 256, 214272>>>(Wh, bh);                     // launch 6
    k_final<<<dim3(64, 4), 256>>>(lin_W, lin_b, lin_a1, lin_a2, out);
    k_obsout<<<NES, 256>>>(obs_b, obs_a, out);
}